// round 3
// baseline (speedup 1.0000x reference)
#include <cuda_runtime.h>
#include <math.h>

#define BATCH 512
#define SEQ   512
#define EMBED 256
#define OUTC  5
#define EV4   (EMBED / 4)   // 64 float4 per embedding row
#define CH    4             // chunks per sample
#define CHTOK (SEQ / CH)    // 128 tokens per chunk

// Device scratch (mallocs forbidden). Counters are zero at load and reset
// inside the kernel every call -> graph-replay safe.
__device__ float4       g_part[BATCH * CH * EV4];  // partial pooled vectors, 2 MB
__device__ float        g_loss[BATCH];
__device__ unsigned int g_scnt[BATCH];             // per-sample chunk counters
__device__ unsigned int g_count;                   // global sample counter

__device__ __forceinline__ void acc4(float4& a, const float4& v) {
    a.x += v.x; a.y += v.y; a.z += v.z; a.w += v.w;
}

__global__ __launch_bounds__(256, 4)
void pool_loss_kernel(const int*   __restrict__ input_x,
                      const int*   __restrict__ lengths,
                      const int*   __restrict__ input_y,
                      const float* __restrict__ emb,
                      const float* __restrict__ W,
                      const float* __restrict__ bias,
                      float*       __restrict__ out)
{
    __shared__ int    s_idx[CHTOK];
    __shared__ float4 s_acc[256];
    __shared__ float  s_red[OUTC][2];
    __shared__ float  s_sum[256];
    __shared__ int    s_flag, s_last;

    const int bc  = blockIdx.x;
    const int b   = bc >> 2;      // sample
    const int c   = bc & 3;       // chunk within sample
    const int tid = threadIdx.x;
    const int len = lengths[b];

    const int base  = c * CHTOK;
    int count = len - base;
    if (count < 0)     count = 0;
    if (count > CHTOK) count = CHTOK;

    // Stage this chunk's token ids in shared
    if (tid < count) s_idx[tid] = input_x[b * SEQ + base + tid];
    __syncthreads();

    const int g = tid >> 6;   // token group 0..3
    const int l = tid & 63;   // float4 lane within row

    const float4* __restrict__ embv = (const float4*)emb;

    float4 a0 = make_float4(0.f, 0.f, 0.f, 0.f);
    float4 a1 = make_float4(0.f, 0.f, 0.f, 0.f);
    float4 a2 = make_float4(0.f, 0.f, 0.f, 0.f);
    float4 a3 = make_float4(0.f, 0.f, 0.f, 0.f);

    int s = g;
    // 4 independent gathers in flight per thread
    for (; s + 12 < count; s += 16) {
        const int t0 = s_idx[s];
        const int t1 = s_idx[s + 4];
        const int t2 = s_idx[s + 8];
        const int t3 = s_idx[s + 12];
        float4 v0 = embv[(long)t0 * EV4 + l];
        float4 v1 = embv[(long)t1 * EV4 + l];
        float4 v2 = embv[(long)t2 * EV4 + l];
        float4 v3 = embv[(long)t3 * EV4 + l];
        acc4(a0, v0); acc4(a1, v1); acc4(a2, v2); acc4(a3, v3);
    }
    for (; s < count; s += 4) {
        const int t = s_idx[s];
        float4 v = embv[(long)t * EV4 + l];
        acc4(a0, v);
    }
    acc4(a0, a1); acc4(a2, a3); acc4(a0, a2);

    s_acc[tid] = a0;
    __syncthreads();

    // Combine the 4 token groups; write this chunk's partial pooled vector
    if (tid < 64) {
        float4 p0 = s_acc[l];
        float4 p1 = s_acc[64 + l];
        float4 p2 = s_acc[128 + l];
        float4 p3 = s_acc[192 + l];
        float4 p;
        p.x = (p0.x + p1.x) + (p2.x + p3.x);
        p.y = (p0.y + p1.y) + (p2.y + p3.y);
        p.z = (p0.z + p1.z) + (p2.z + p3.z);
        p.w = (p0.w + p1.w) + (p2.w + p3.w);
        g_part[bc * EV4 + l] = p;
    }
    if (tid == 0) {
        __threadfence();
        s_flag = (atomicAdd(&g_scnt[b], 1u) == CH - 1) ? 1 : 0;
    }
    __syncthreads();

    if (!s_flag) return;   // uniform per CTA

    // ---- Last chunk CTA of sample b: finalize this sample ----
    if (tid == 0) g_scnt[b] = 0;          // reset for next replay
    __threadfence();                      // order counter-observe before reads

    float part[OUTC];
    if (tid < 64) {
        // Deterministic fixed-order combine of the 4 chunk partials
        float4 q0 = g_part[(b * CH + 0) * EV4 + l];
        float4 q1 = g_part[(b * CH + 1) * EV4 + l];
        float4 q2 = g_part[(b * CH + 2) * EV4 + l];
        float4 q3 = g_part[(b * CH + 3) * EV4 + l];
        float4 pooled;
        pooled.x = (q0.x + q1.x) + (q2.x + q3.x);
        pooled.y = (q0.y + q1.y) + (q2.y + q3.y);
        pooled.z = (q0.z + q1.z) + (q2.z + q3.z);
        pooled.w = (q0.w + q1.w) + (q2.w + q3.w);

        const float4* __restrict__ Wv = (const float4*)W;
        #pragma unroll
        for (int o = 0; o < OUTC; o++) {
            float4 w = Wv[o * EV4 + l];
            part[o] = pooled.x * w.x + pooled.y * w.y
                    + pooled.z * w.z + pooled.w * w.w;
        }
        #pragma unroll
        for (int o = 0; o < OUTC; o++) {
            float v = part[o];
            #pragma unroll
            for (int off = 16; off > 0; off >>= 1)
                v += __shfl_down_sync(0xffffffffu, v, off);
            part[o] = v;
        }
        if ((tid & 31) == 0) {
            const int w = tid >> 5;  // 0 or 1
            #pragma unroll
            for (int o = 0; o < OUTC; o++) s_red[o][w] = part[o];
        }
    }
    __syncthreads();

    if (tid == 0) {
        const float inv_len = 1.0f / (float)len;
        float logits[OUTC];
        float m = -INFINITY;
        #pragma unroll
        for (int o = 0; o < OUTC; o++) {
            logits[o] = (s_red[o][0] + s_red[o][1]) * inv_len + bias[o];
            m = fmaxf(m, logits[o]);
        }
        float se = 0.f;
        #pragma unroll
        for (int o = 0; o < OUTC; o++) se += __expf(logits[o] - m);
        const float lse = m + __logf(se);
        const int y = input_y[b];
        g_loss[b] = lse - logits[y];
        __threadfence();
        s_last = (atomicAdd(&g_count, 1u) == BATCH - 1) ? 1 : 0;
    }
    __syncthreads();

    // ---- Globally last sample-finalizer: mean over 512 losses ----
    if (s_last) {
        __threadfence();
        s_sum[tid] = g_loss[tid] + g_loss[tid + 256];
        __syncthreads();
        #pragma unroll
        for (int off = 128; off > 0; off >>= 1) {
            if (tid < off) s_sum[tid] += s_sum[tid + off];
            __syncthreads();
        }
        if (tid == 0) {
            out[0] = s_sum[0] * (1.0f / (float)BATCH);
            g_count = 0;   // reset for next replay
        }
    }
}

extern "C" void kernel_launch(void* const* d_in, const int* in_sizes, int n_in,
                              void* d_out, int out_size)
{
    const int*   input_x = (const int*)d_in[0];
    const int*   lengths = (const int*)d_in[1];
    const int*   input_y = (const int*)d_in[2];
    const float* emb     = (const float*)d_in[3];
    const float* W       = (const float*)d_in[4];
    const float* bias    = (const float*)d_in[5];
    float* out = (float*)d_out;

    pool_loss_kernel<<<BATCH * CH, 256>>>(input_x, lengths, input_y, emb, W, bias, out);
}

// round 4
// speedup vs baseline: 1.0031x; 1.0031x over previous
#include <cuda_runtime.h>
#include <math.h>

#define BATCH 512
#define SEQ   512
#define EMBED 256
#define OUTC  5
#define EV4   (EMBED / 4)   // 64 float4 per embedding row
#define CH    2             // halves per sample
#define CHTOK (SEQ / CH)    // 256 tokens per half

// Device scratch (mallocs forbidden). Counters zero at load, reset in-kernel
// every call -> graph-replay safe.
__device__ float4       g_part[BATCH * CH * EV4];  // 1 MB partial pooled vecs
__device__ float        g_loss[BATCH];
__device__ unsigned int g_scnt[BATCH];
__device__ unsigned int g_count;

__device__ __forceinline__ void acc4(float4& a, const float4& v) {
    a.x += v.x; a.y += v.y; a.z += v.z; a.w += v.w;
}

__global__ __launch_bounds__(256, 4)
void pool_loss_kernel(const int*   __restrict__ input_x,
                      const int*   __restrict__ lengths,
                      const int*   __restrict__ input_y,
                      const float* __restrict__ emb,
                      const float* __restrict__ W,
                      const float* __restrict__ bias,
                      float*       __restrict__ out)
{
    __shared__ int    s_idx[CHTOK];
    __shared__ float4 s_acc[256];
    __shared__ float  s_red[OUTC][2];
    __shared__ float  s_sum[256];
    __shared__ int    s_flag, s_last;

    const int bc  = blockIdx.x;
    const int b   = bc >> 1;      // sample
    const int h   = bc & 1;       // half
    const int tid = threadIdx.x;
    const int len = lengths[b];

    const int base  = h * CHTOK;
    int count = len - base;
    if (count < 0)     count = 0;
    if (count > CHTOK) count = CHTOK;

    // Stage this half's token ids in shared
    if (tid < count) s_idx[tid] = input_x[b * SEQ + base + tid];
    __syncthreads();

    const int g = tid >> 6;   // token group 0..3
    const int l = tid & 63;   // float4 lane within row

    const float4* __restrict__ embv = (const float4*)emb;

    float4 a0 = make_float4(0.f, 0.f, 0.f, 0.f);
    float4 a1 = make_float4(0.f, 0.f, 0.f, 0.f);
    float4 a2 = make_float4(0.f, 0.f, 0.f, 0.f);
    float4 a3 = make_float4(0.f, 0.f, 0.f, 0.f);

    int s = g;
    // 8 independent gathers in flight per thread (MLP=8)
    for (; s + 28 < count; s += 32) {
        const int t0 = s_idx[s];
        const int t1 = s_idx[s + 4];
        const int t2 = s_idx[s + 8];
        const int t3 = s_idx[s + 12];
        const int t4 = s_idx[s + 16];
        const int t5 = s_idx[s + 20];
        const int t6 = s_idx[s + 24];
        const int t7 = s_idx[s + 28];
        float4 v0 = embv[(long)t0 * EV4 + l];
        float4 v1 = embv[(long)t1 * EV4 + l];
        float4 v2 = embv[(long)t2 * EV4 + l];
        float4 v3 = embv[(long)t3 * EV4 + l];
        float4 v4 = embv[(long)t4 * EV4 + l];
        float4 v5 = embv[(long)t5 * EV4 + l];
        float4 v6 = embv[(long)t6 * EV4 + l];
        float4 v7 = embv[(long)t7 * EV4 + l];
        acc4(a0, v0); acc4(a1, v1); acc4(a2, v2); acc4(a3, v3);
        acc4(a0, v4); acc4(a1, v5); acc4(a2, v6); acc4(a3, v7);
    }
    for (; s < count; s += 4) {
        const int t = s_idx[s];
        float4 v = embv[(long)t * EV4 + l];
        acc4(a0, v);
    }
    acc4(a0, a1); acc4(a2, a3); acc4(a0, a2);

    s_acc[tid] = a0;
    __syncthreads();

    // Combine token groups; write this half's partial pooled vector
    if (tid < 64) {
        float4 p0 = s_acc[l];
        float4 p1 = s_acc[64 + l];
        float4 p2 = s_acc[128 + l];
        float4 p3 = s_acc[192 + l];
        float4 p;
        p.x = (p0.x + p1.x) + (p2.x + p3.x);
        p.y = (p0.y + p1.y) + (p2.y + p3.y);
        p.z = (p0.z + p1.z) + (p2.z + p3.z);
        p.w = (p0.w + p1.w) + (p2.w + p3.w);
        g_part[bc * EV4 + l] = p;
    }
    if (tid == 0) {
        __threadfence();
        s_flag = (atomicAdd(&g_scnt[b], 1u) == CH - 1) ? 1 : 0;
    }
    __syncthreads();

    if (!s_flag) return;   // uniform per CTA

    // ---- Second-arriving half: finalize sample b ----
    if (tid == 0) g_scnt[b] = 0;   // reset for next replay
    __threadfence();               // acquire: order partial reads after count

    float part[OUTC];
    if (tid < 64) {
        float4 q0 = g_part[(b * CH + 0) * EV4 + l];
        float4 q1 = g_part[(b * CH + 1) * EV4 + l];
        float4 pooled;
        pooled.x = q0.x + q1.x;
        pooled.y = q0.y + q1.y;
        pooled.z = q0.z + q1.z;
        pooled.w = q0.w + q1.w;

        const float4* __restrict__ Wv = (const float4*)W;
        #pragma unroll
        for (int o = 0; o < OUTC; o++) {
            float4 w = Wv[o * EV4 + l];
            part[o] = pooled.x * w.x + pooled.y * w.y
                    + pooled.z * w.z + pooled.w * w.w;
        }
        #pragma unroll
        for (int o = 0; o < OUTC; o++) {
            float v = part[o];
            #pragma unroll
            for (int off = 16; off > 0; off >>= 1)
                v += __shfl_down_sync(0xffffffffu, v, off);
            part[o] = v;
        }
        if ((tid & 31) == 0) {
            const int w = tid >> 5;  // 0 or 1
            #pragma unroll
            for (int o = 0; o < OUTC; o++) s_red[o][w] = part[o];
        }
    }
    __syncthreads();

    if (tid == 0) {
        const float inv_len = 1.0f / (float)len;
        float logits[OUTC];
        float m = -INFINITY;
        #pragma unroll
        for (int o = 0; o < OUTC; o++) {
            logits[o] = (s_red[o][0] + s_red[o][1]) * inv_len + bias[o];
            m = fmaxf(m, logits[o]);
        }
        float se = 0.f;
        #pragma unroll
        for (int o = 0; o < OUTC; o++) se += __expf(logits[o] - m);
        const float lse = m + __logf(se);
        const int y = input_y[b];
        g_loss[b] = lse - logits[y];
        __threadfence();
        s_last = (atomicAdd(&g_count, 1u) == BATCH - 1) ? 1 : 0;
    }
    __syncthreads();

    // ---- Globally last finalizer: mean over 512 losses ----
    if (s_last) {
        __threadfence();
        s_sum[tid] = g_loss[tid] + g_loss[tid + 256];
        __syncthreads();
        #pragma unroll
        for (int off = 128; off > 0; off >>= 1) {
            if (tid < off) s_sum[tid] += s_sum[tid + off];
            __syncthreads();
        }
        if (tid == 0) {
            out[0] = s_sum[0] * (1.0f / (float)BATCH);
            g_count = 0;   // reset for next replay
        }
    }
}

extern "C" void kernel_launch(void* const* d_in, const int* in_sizes, int n_in,
                              void* d_out, int out_size)
{
    const int*   input_x = (const int*)d_in[0];
    const int*   lengths = (const int*)d_in[1];
    const int*   input_y = (const int*)d_in[2];
    const float* emb     = (const float*)d_in[3];
    const float* W       = (const float*)d_in[4];
    const float* bias    = (const float*)d_in[5];
    float* out = (float*)d_out;

    pool_loss_kernel<<<BATCH * CH, 256>>>(input_x, lengths, input_y, emb, W, bias, out);
}

// round 5
// speedup vs baseline: 1.0933x; 1.0900x over previous
#include <cuda_runtime.h>
#include <math.h>

#define BATCH 512
#define SEQ   512
#define EMBED 256
#define OUTC  5
#define EV4   (EMBED / 4)   // 64 float4 per embedding row

// Scratch (device mallocs forbidden). g_count zero at load, reset in-kernel
// every call -> graph-replay safe.
__device__ float        g_loss[BATCH];
__device__ unsigned int g_count;

__device__ __forceinline__ void acc4(float4& a, const float4& v) {
    a.x += v.x; a.y += v.y; a.z += v.z; a.w += v.w;
}

__global__ __launch_bounds__(256, 4)
void pool_loss_kernel(const int*   __restrict__ input_x,
                      const int*   __restrict__ lengths,
                      const int*   __restrict__ input_y,
                      const float* __restrict__ emb,
                      const float* __restrict__ W,
                      const float* __restrict__ bias,
                      float*       __restrict__ out)
{
    __shared__ int    s_idx[SEQ];
    __shared__ float4 s_acc[256];
    __shared__ float  s_red[OUTC][2];
    __shared__ float  s_sum[256];
    __shared__ int    s_last;

    const int b   = blockIdx.x;
    const int tid = threadIdx.x;
    const int len = lengths[b];

    // Stage this sample's token ids in shared (2 KB)
    const int* xrow = input_x + b * SEQ;
    s_idx[tid]       = xrow[tid];
    s_idx[tid + 256] = xrow[tid + 256];
    __syncthreads();

    const int g = tid >> 6;   // token group 0..3
    const int l = tid & 63;   // float4 lane within row

    const float4* __restrict__ embv = (const float4*)emb;

    float4 a0 = make_float4(0.f, 0.f, 0.f, 0.f);
    float4 a1 = make_float4(0.f, 0.f, 0.f, 0.f);
    float4 a2 = make_float4(0.f, 0.f, 0.f, 0.f);
    float4 a3 = make_float4(0.f, 0.f, 0.f, 0.f);

    int s = g;
    // 8 independent gathers in flight per thread (MLP=8): 32 tokens/iter
    for (; s + 28 < len; s += 32) {
        const int t0 = s_idx[s];
        const int t1 = s_idx[s + 4];
        const int t2 = s_idx[s + 8];
        const int t3 = s_idx[s + 12];
        const int t4 = s_idx[s + 16];
        const int t5 = s_idx[s + 20];
        const int t6 = s_idx[s + 24];
        const int t7 = s_idx[s + 28];
        float4 v0 = embv[(long)t0 * EV4 + l];
        float4 v1 = embv[(long)t1 * EV4 + l];
        float4 v2 = embv[(long)t2 * EV4 + l];
        float4 v3 = embv[(long)t3 * EV4 + l];
        float4 v4 = embv[(long)t4 * EV4 + l];
        float4 v5 = embv[(long)t5 * EV4 + l];
        float4 v6 = embv[(long)t6 * EV4 + l];
        float4 v7 = embv[(long)t7 * EV4 + l];
        acc4(a0, v0); acc4(a1, v1); acc4(a2, v2); acc4(a3, v3);
        acc4(a0, v4); acc4(a1, v5); acc4(a2, v6); acc4(a3, v7);
    }
    // Mid tail: 4 in flight (16 tokens/iter)
    for (; s + 12 < len; s += 16) {
        const int t0 = s_idx[s];
        const int t1 = s_idx[s + 4];
        const int t2 = s_idx[s + 8];
        const int t3 = s_idx[s + 12];
        float4 v0 = embv[(long)t0 * EV4 + l];
        float4 v1 = embv[(long)t1 * EV4 + l];
        float4 v2 = embv[(long)t2 * EV4 + l];
        float4 v3 = embv[(long)t3 * EV4 + l];
        acc4(a0, v0); acc4(a1, v1); acc4(a2, v2); acc4(a3, v3);
    }
    // Final tail
    for (; s < len; s += 4) {
        const int t = s_idx[s];
        float4 v = embv[(long)t * EV4 + l];
        acc4(a0, v);
    }
    acc4(a0, a1); acc4(a2, a3); acc4(a0, a2);

    s_acc[tid] = a0;
    __syncthreads();

    // Warps 0-1 (tid < 64): combine groups, dot with W
    float part[OUTC];
    if (tid < 64) {
        float4 p0 = s_acc[l];
        float4 p1 = s_acc[64 + l];
        float4 p2 = s_acc[128 + l];
        float4 p3 = s_acc[192 + l];
        float4 pooled;
        pooled.x = (p0.x + p1.x) + (p2.x + p3.x);
        pooled.y = (p0.y + p1.y) + (p2.y + p3.y);
        pooled.z = (p0.z + p1.z) + (p2.z + p3.z);
        pooled.w = (p0.w + p1.w) + (p2.w + p3.w);

        const float4* __restrict__ Wv = (const float4*)W;
        #pragma unroll
        for (int o = 0; o < OUTC; o++) {
            float4 w = Wv[o * EV4 + l];
            part[o] = pooled.x * w.x + pooled.y * w.y
                    + pooled.z * w.z + pooled.w * w.w;
        }
        #pragma unroll
        for (int o = 0; o < OUTC; o++) {
            float v = part[o];
            #pragma unroll
            for (int off = 16; off > 0; off >>= 1)
                v += __shfl_down_sync(0xffffffffu, v, off);
            part[o] = v;
        }
        if ((tid & 31) == 0) {
            const int w = tid >> 5;  // 0 or 1
            #pragma unroll
            for (int o = 0; o < OUTC; o++) s_red[o][w] = part[o];
        }
    }
    __syncthreads();

    // Per-sample loss + last-block handoff
    if (tid == 0) {
        const float inv_len = 1.0f / (float)len;
        float logits[OUTC];
        float m = -INFINITY;
        #pragma unroll
        for (int o = 0; o < OUTC; o++) {
            logits[o] = (s_red[o][0] + s_red[o][1]) * inv_len + bias[o];
            m = fmaxf(m, logits[o]);
        }
        float se = 0.f;
        #pragma unroll
        for (int o = 0; o < OUTC; o++) se += __expf(logits[o] - m);
        const float lse = m + __logf(se);
        const int y = input_y[b];
        g_loss[b] = lse - logits[y];
        __threadfence();
        s_last = (atomicAdd(&g_count, 1u) == BATCH - 1) ? 1 : 0;
    }
    __syncthreads();

    // Last block to finish: mean over 512 losses
    if (s_last) {
        __threadfence();
        s_sum[tid] = g_loss[tid] + g_loss[tid + 256];
        __syncthreads();
        #pragma unroll
        for (int off = 128; off > 0; off >>= 1) {
            if (tid < off) s_sum[tid] += s_sum[tid + off];
            __syncthreads();
        }
        if (tid == 0) {
            out[0] = s_sum[0] * (1.0f / (float)BATCH);
            g_count = 0;   // reset for next replay
        }
    }
}

extern "C" void kernel_launch(void* const* d_in, const int* in_sizes, int n_in,
                              void* d_out, int out_size)
{
    const int*   input_x = (const int*)d_in[0];
    const int*   lengths = (const int*)d_in[1];
    const int*   input_y = (const int*)d_in[2];
    const float* emb     = (const float*)d_in[3];
    const float* W       = (const float*)d_in[4];
    const float* bias    = (const float*)d_in[5];
    float* out = (float*)d_out;

    pool_loss_kernel<<<BATCH, 256>>>(input_x, lengths, input_y, emb, W, bias, out);
}